// round 5
// baseline (speedup 1.0000x reference)
#include <cuda_runtime.h>
#include <math.h>

#define ANGR 9
#define NVIEW 81
#define HH 96
#define WW 96
#define HW 9216
#define CF 7
#define BB 2

static const float NINIT_F = 2.0f * 81.0f * 9216.0f;  // 1492992
static const float NAGG_F  = 2.0f * 9216.0f;          // 18432

// ---------------- device scratch (no allocations allowed) ----------------
__device__ float g_fA[BB * CF * NVIEW * HW];   // 41.8 MB
__device__ float g_fB[BB * CF * NVIEW * HW];   // 41.8 MB
__device__ float g_y0[BB * 180 * HW];          // 13.3 MB
__device__ float g_y1[BB * 180 * HW];          // 13.3 MB
__device__ float g_acc[18 * 2 * 192];          // per-layer [sum, sumsq] per channel
__device__ float g_ss [18 * 2 * 192];          // per-layer [scale, shift] per channel

// ---------------- zero the stat accumulators ----------------
__global__ void k_zero() {
    int t = blockIdx.x * blockDim.x + threadIdx.x;
    if (t < 18 * 2 * 192) g_acc[t] = 0.f;
}

// ---------------- BN finalize: scale/shift from batch stats ----------------
__global__ void k_bnfin(int L, int C, float N,
                        const float* __restrict__ gamma,
                        const float* __restrict__ beta) {
    int c = threadIdx.x;
    if (c < C) {
        float s = g_acc[(L * 2 + 0) * 192 + c];
        float q = g_acc[(L * 2 + 1) * 192 + c];
        float m = s / N;
        float var = fmaxf(q / N - m * m, 0.f);
        float sc = gamma[c] * rsqrtf(var + 1e-5f);
        g_ss[(L * 2 + 0) * 192 + c] = sc;
        g_ss[(L * 2 + 1) * 192 + c] = beta[c] - m * sc;
    }
}

// ---------------- per-view 3x3 conv (the dilated MacPI convs in SAI space) ----
// block (96,2): tx = column j, each thread computes 4 consecutive rows x 7 cout.
// grid (12, 81, 2): row-tile of 8, view, batch.
template<int CIN, bool FROM_X, bool ACT>
__global__ __launch_bounds__(192)
void k_conv3x3(const float* __restrict__ in, float* __restrict__ out,
               const float* __restrict__ w, int ssIn, int statL) {
    __shared__ float sW[CF * CIN * 9];
    __shared__ float sSc[CIN > 0 ? CIN : 1], sSh[CIN > 0 ? CIN : 1];
    __shared__ float sPart[6][14];

    int t = threadIdx.y * 96 + threadIdx.x;
    for (int s = t; s < CF * CIN * 9; s += 192) sW[s] = w[s];
    if (ACT && t < CIN) {
        sSc[t] = g_ss[(ssIn * 2 + 0) * 192 + t];
        sSh[t] = g_ss[(ssIn * 2 + 1) * 192 + t];
    }
    __syncthreads();

    int b = blockIdx.z, view = blockIdx.y;
    int j = threadIdx.x;
    int i0 = blockIdx.x * 8 + threadIdx.y * 4;

    const float* ibase;
    if (FROM_X)
        ibase = in + (size_t)b * 864 * 864 + (size_t)(view / ANGR) * 96 * 864 + (size_t)(view % ANGR) * 96;
    else
        ibase = in + ((size_t)(b * CF) * NVIEW + view) * HW;

    float acc[CF][4];
#pragma unroll
    for (int co = 0; co < CF; ++co)
#pragma unroll
        for (int p = 0; p < 4; ++p) acc[co][p] = 0.f;

#pragma unroll
    for (int cin = 0; cin < CIN; ++cin) {
        const float* ip = FROM_X ? ibase : (ibase + (size_t)cin * NVIEW * HW);
        float colv[3][6];
#pragma unroll
        for (int rr = 0; rr < 6; ++rr) {
            int i = i0 - 1 + rr;
#pragma unroll
            for (int cc = 0; cc < 3; ++cc) {
                int jj = j - 1 + cc;
                float v = 0.f;
                if (i >= 0 && i < HH && jj >= 0 && jj < WW) {
                    v = FROM_X ? ip[i * 864 + jj] : ip[i * WW + jj];
                    if (ACT) v = fmaxf(fmaf(v, sSc[cin], sSh[cin]), 0.f);
                }
                colv[cc][rr] = v;
            }
        }
#pragma unroll
        for (int ky = 0; ky < 3; ++ky)
#pragma unroll
            for (int kx = 0; kx < 3; ++kx) {
                float wr[CF];
#pragma unroll
                for (int co = 0; co < CF; ++co)
                    wr[co] = sW[((co * CIN + cin) * 3 + ky) * 3 + kx];
#pragma unroll
                for (int p = 0; p < 4; ++p) {
                    float v = colv[kx][p + ky];
#pragma unroll
                    for (int co = 0; co < CF; ++co)
                        acc[co][p] = fmaf(v, wr[co], acc[co][p]);
                }
            }
    }

    float ls[CF], ls2[CF];
#pragma unroll
    for (int co = 0; co < CF; ++co) { ls[co] = 0.f; ls2[co] = 0.f; }
#pragma unroll
    for (int co = 0; co < CF; ++co) {
        float* op = out + ((size_t)(b * CF + co) * NVIEW + view) * HW + j;
#pragma unroll
        for (int p = 0; p < 4; ++p) {
            float y = acc[co][p];
            op[(i0 + p) * WW] = y;
            ls[co] += y; ls2[co] += y * y;
        }
    }

    int lane = t & 31, warp = t >> 5;
#pragma unroll
    for (int co = 0; co < CF; ++co) {
        float s = ls[co], q = ls2[co];
#pragma unroll
        for (int off = 16; off > 0; off >>= 1) {
            s += __shfl_xor_sync(0xffffffffu, s, off);
            q += __shfl_xor_sync(0xffffffffu, q, off);
        }
        if (lane == 0) { sPart[warp][co] = s; sPart[warp][7 + co] = q; }
    }
    __syncthreads();
    if (t < 14) {
        float tot = 0.f;
#pragma unroll
        for (int wp = 0; wp < 6; ++wp) tot += sPart[wp][t];
        int isQ = t / 7, co = t % 7;
        atomicAdd(&g_acc[(statL * 2 + isQ) * 192 + co], tot);
    }
}

// ---------------- fused disp_shift + BuildCost (plane sweep) ----------------
// grid (9 tiles, 9 groups, 2 batch), block 256, dynamic smem: weights + tile.
__global__ __launch_bounds__(256)
void k_buildcost(const float* __restrict__ f, float* __restrict__ cv,
                 const float* __restrict__ bcw, int ssIn) {
    extern __shared__ float sm[];
    float* sW = sm;            // 81*7*16 = 9072 floats
    float* sT = sm + 9072;     // 7*32*32 = 7168 floats
    __shared__ float sSc[CF], sSh[CF];

    int t = threadIdx.x;
    int b = blockIdx.z, g = blockIdx.y;
    int d = g - 4;
    int y0 = (blockIdx.x / 3) * 32, x0 = (blockIdx.x % 3) * 32;

    if (t < CF) {
        sSc[t] = g_ss[(ssIn * 2 + 0) * 192 + t];
        sSh[t] = g_ss[(ssIn * 2 + 1) * 192 + t];
    }
    // weight layout in smem: [uv][c][o]; apply view flip for d>0
    for (int s = t; s < 9072; s += 256) {
        int o = s & 15;
        int c = (s >> 4) % 7;
        int uv = s / 112;
        int u = uv / 9, v = uv % 9;
        int uvs = (d > 0) ? ((8 - u) * 9 + (8 - v)) : uv;
        sW[s] = bcw[((size_t)(16 * g + o) * 7 + c) * 81 + uvs];
    }
    __syncthreads();

    int tx = t & 31, ty0 = t >> 5;  // ty0 in 0..7
    float acc[4][16];
#pragma unroll
    for (int p = 0; p < 4; ++p)
#pragma unroll
        for (int o = 0; o < 16; ++o) acc[p][o] = 0.f;

    const float* fb = f + (size_t)b * CF * NVIEW * HW;

    for (int uv = 0; uv < 81; ++uv) {
        int u = uv / 9, v = uv % 9;
        int sy = y0 - d * (u - 4), sx = x0 - d * (v - 4);
        for (int s = t; s < 7168; s += 256) {
            int c = s >> 10;
            int pp = s & 1023;
            int r = pp >> 5, cc = pp & 31;
            int ii = sy + r, jj = sx + cc;
            float val = 0.f;
            if (ii >= 0 && ii < HH && jj >= 0 && jj < WW)
                val = fmaxf(fmaf(fb[((size_t)c * NVIEW + uv) * HW + ii * WW + jj],
                                 sSc[c], sSh[c]), 0.f);
            sT[s] = val;
        }
        __syncthreads();
        const float* wuv = sW + uv * 112;
#pragma unroll
        for (int c = 0; c < 7; ++c) {
            float wr[16];
#pragma unroll
            for (int o = 0; o < 16; ++o) wr[o] = wuv[c * 16 + o];
#pragma unroll
            for (int p = 0; p < 4; ++p) {
                float v = sT[c * 1024 + (ty0 + 8 * p) * 32 + tx];
#pragma unroll
                for (int o = 0; o < 16; ++o)
                    acc[p][o] = fmaf(v, wr[o], acc[p][o]);
            }
        }
        __syncthreads();
    }

#pragma unroll
    for (int o = 0; o < 16; ++o) {
        float* op = cv + ((size_t)b * 144 + 16 * g + o) * HW;
#pragma unroll
        for (int p = 0; p < 4; ++p)
            op[(y0 + ty0 + 8 * p) * WW + (x0 + tx)] = acc[p][o];
    }
}

// ---------------- depthwise 3x3 (pad 1), optional input BN+ReLU ------------
__global__ __launch_bounds__(256)
void k_dw(const float* __restrict__ in, float* __restrict__ out,
          const float* __restrict__ w, int C, int ssIn, int statL) {
    int c = blockIdx.x, b = blockIdx.y, t = threadIdx.x;
    float wr[9];
#pragma unroll
    for (int k = 0; k < 9; ++k) wr[k] = w[c * 9 + k];
    float sc = 1.f, sh = 0.f;
    bool act = (ssIn >= 0);
    if (act) { sc = g_ss[(ssIn * 2 + 0) * 192 + c]; sh = g_ss[(ssIn * 2 + 1) * 192 + c]; }
    const float* ip = in + ((size_t)b * C + c) * HW;
    float* op = out + ((size_t)b * C + c) * HW;
    float ls = 0.f, ls2 = 0.f;
    for (int p = t; p < HW; p += 256) {
        int i = p / 96, j = p - i * 96;
        float sum = 0.f;
#pragma unroll
        for (int dy = -1; dy <= 1; ++dy)
#pragma unroll
            for (int dx = -1; dx <= 1; ++dx) {
                int ii = i + dy, jj = j + dx;
                if (ii >= 0 && ii < HH && jj >= 0 && jj < WW) {
                    float v = ip[ii * WW + jj];
                    if (act) v = fmaxf(fmaf(v, sc, sh), 0.f);
                    sum = fmaf(v, wr[(dy + 1) * 3 + dx + 1], sum);
                }
            }
        op[p] = sum; ls += sum; ls2 += sum * sum;
    }
    __shared__ float sP[8][2];
    int lane = t & 31, wp = t >> 5;
#pragma unroll
    for (int off = 16; off > 0; off >>= 1) {
        ls  += __shfl_xor_sync(0xffffffffu, ls, off);
        ls2 += __shfl_xor_sync(0xffffffffu, ls2, off);
    }
    if (lane == 0) { sP[wp][0] = ls; sP[wp][1] = ls2; }
    __syncthreads();
    if (t == 0) {
        float a = 0.f, q = 0.f;
#pragma unroll
        for (int k = 0; k < 8; ++k) { a += sP[k][0]; q += sP[k][1]; }
        atomicAdd(&g_acc[(statL * 2 + 0) * 192 + c], a);
        atomicAdd(&g_acc[(statL * 2 + 1) * 192 + c], q);
    }
}

// ---------------- pointwise conv = GEMM [Cout x Cin] x [Cin x 9216] --------
// BM=64 (cout) x BN=64 (pix) x BK=16; 256 threads, 4x4 per thread.
__global__ __launch_bounds__(256)
void k_pw(const float* __restrict__ in, float* __restrict__ out,
          const float* __restrict__ w, int Cin, int Cout, int ssIn, int statL) {
    __shared__ __align__(16) float sA[16 * 64];
    __shared__ __align__(16) float sB[16 * 64];
    __shared__ float sSc[192], sSh[192];
    int t = threadIdx.x;
    int n0 = blockIdx.x * 64, m0 = blockIdx.y * 64, b = blockIdx.z;
    for (int c = t; c < Cin; c += 256) {
        sSc[c] = g_ss[(ssIn * 2 + 0) * 192 + c];
        sSh[c] = g_ss[(ssIn * 2 + 1) * 192 + c];
    }
    int tm = (t >> 4) << 2, tn = (t & 15) << 2;
    float acc[4][4];
#pragma unroll
    for (int i2 = 0; i2 < 4; ++i2)
#pragma unroll
        for (int j2 = 0; j2 < 4; ++j2) acc[i2][j2] = 0.f;
    int Kt = (Cin + 15) >> 4;
    __syncthreads();
    for (int kt = 0; kt < Kt; ++kt) {
        int k0 = kt << 4;
#pragma unroll
        for (int r = 0; r < 4; ++r) {
            int s = t + r * 256;
            int k = s >> 6, mn = s & 63;
            int ci = k0 + k;
            int co = m0 + mn;
            sA[s] = (ci < Cin && co < Cout) ? w[(size_t)co * Cin + ci] : 0.f;
            float xv = 0.f;
            if (ci < Cin)
                xv = fmaxf(fmaf(in[((size_t)b * Cin + ci) * HW + n0 + mn], sSc[ci], sSh[ci]), 0.f);
            sB[s] = xv;
        }
        __syncthreads();
#pragma unroll
        for (int kk = 0; kk < 16; ++kk) {
            float4 av = *reinterpret_cast<const float4*>(&sA[kk * 64 + tm]);
            float4 bv = *reinterpret_cast<const float4*>(&sB[kk * 64 + tn]);
            float a[4] = {av.x, av.y, av.z, av.w};
            float bb2[4] = {bv.x, bv.y, bv.z, bv.w};
#pragma unroll
            for (int i2 = 0; i2 < 4; ++i2)
#pragma unroll
                for (int j2 = 0; j2 < 4; ++j2)
                    acc[i2][j2] = fmaf(a[i2], bb2[j2], acc[i2][j2]);
        }
        __syncthreads();
    }
    float ls[4], ls2[4];
#pragma unroll
    for (int i2 = 0; i2 < 4; ++i2) { ls[i2] = 0.f; ls2[i2] = 0.f; }
#pragma unroll
    for (int i2 = 0; i2 < 4; ++i2) {
        int co = m0 + tm + i2;
        if (co < Cout) {
            float* op = out + ((size_t)b * Cout + co) * HW + n0 + tn;
#pragma unroll
            for (int j2 = 0; j2 < 4; ++j2) {
                float y = acc[i2][j2];
                op[j2] = y; ls[i2] += y; ls2[i2] += y * y;
            }
        }
    }
    if (statL >= 0) {
#pragma unroll
        for (int i2 = 0; i2 < 4; ++i2) {
            float s = ls[i2], q = ls2[i2];
#pragma unroll
            for (int off = 8; off > 0; off >>= 1) {
                s += __shfl_xor_sync(0xffffffffu, s, off);
                q += __shfl_xor_sync(0xffffffffu, q, off);
            }
            if ((t & 15) == 0) {
                int co = m0 + tm + i2;
                if (co < Cout) {
                    atomicAdd(&g_acc[(statL * 2 + 0) * 192 + co], s);
                    atomicAdd(&g_acc[(statL * 2 + 1) * 192 + co], q);
                }
            }
        }
    }
}

// ---------------- final: pw 180->9 + softmax + disparity expectation -------
__global__ __launch_bounds__(256)
void k_final(const float* __restrict__ in, const float* __restrict__ w,
             int ssIn, float* __restrict__ out) {
    __shared__ float sW[9 * 180];
    __shared__ float sSc[180], sSh[180];
    int t = threadIdx.x;
    for (int s = t; s < 9 * 180; s += 256) sW[s] = w[s];
    for (int c = t; c < 180; c += 256) {
        sSc[c] = g_ss[(ssIn * 2 + 0) * 192 + c];
        sSh[c] = g_ss[(ssIn * 2 + 1) * 192 + c];
    }
    __syncthreads();
    int pix = blockIdx.x * 256 + t;
    int b = pix / HW, p = pix - b * HW;
    float a[9];
#pragma unroll
    for (int c = 0; c < 9; ++c) a[c] = 0.f;
    for (int ci = 0; ci < 180; ++ci) {
        float v = fmaxf(fmaf(in[((size_t)b * 180 + ci) * HW + p], sSc[ci], sSh[ci]), 0.f);
#pragma unroll
        for (int c = 0; c < 9; ++c) a[c] = fmaf(v, sW[c * 180 + ci], a[c]);
    }
    float m = a[0];
#pragma unroll
    for (int c = 1; c < 9; ++c) m = fmaxf(m, a[c]);
    float den = 0.f, num = 0.f;
#pragma unroll
    for (int c = 0; c < 9; ++c) {
        float e = expf(a[c] - m);
        den += e; num += e * (float)(c - 4);
    }
    out[pix] = num / den;
}

// ------------------------------------------------------------------------
extern "C" void kernel_launch(void* const* d_in, const int* in_sizes, int n_in,
                              void* d_out, int out_size) {
    (void)in_sizes; (void)n_in; (void)out_size;
    const float* x       = (const float*)d_in[0];
    const float* fw0     = (const float*)d_in[1];
    const float* fg0     = (const float*)d_in[2];
    const float* fb0     = (const float*)d_in[3];
    const float* fw      = (const float*)d_in[4];
    const float* fg      = (const float*)d_in[5];
    const float* fb      = (const float*)d_in[6];
    const float* bc_w    = (const float*)d_in[7];
    const float* agg0_dw = (const float*)d_in[8];
    const float* agg0_dg = (const float*)d_in[9];
    const float* agg0_db = (const float*)d_in[10];
    const float* agg0_pw = (const float*)d_in[11];
    const float* agg0_pg = (const float*)d_in[12];
    const float* agg0_pb = (const float*)d_in[13];
    const float* aggm_dw = (const float*)d_in[14];
    const float* aggm_dg = (const float*)d_in[15];
    const float* aggm_db = (const float*)d_in[16];
    const float* aggm_pw = (const float*)d_in[17];
    const float* aggm_pg = (const float*)d_in[18];
    const float* aggm_pb = (const float*)d_in[19];
    const float* last_dw = (const float*)d_in[20];
    const float* last_dg = (const float*)d_in[21];
    const float* last_db = (const float*)d_in[22];
    const float* last_pw = (const float*)d_in[23];
    float* out = (float*)d_out;

    float *fA, *fB, *y0, *y1;
    cudaGetSymbolAddress((void**)&fA, g_fA);
    cudaGetSymbolAddress((void**)&fB, g_fB);
    cudaGetSymbolAddress((void**)&y0, g_y0);
    cudaGetSymbolAddress((void**)&y1, g_y1);

    const int bcSmem = (9072 + 7168) * 4;  // 64960 bytes
    cudaFuncSetAttribute(k_buildcost, cudaFuncAttributeMaxDynamicSharedMemorySize, bcSmem);

    k_zero<<<27, 256>>>();

    dim3 cgrid(12, 81, 2), cblk(96, 2);
    // conv0: 1 -> 7, input from x (SAI layout), no input activation
    k_conv3x3<1, true, false><<<cgrid, cblk>>>(x, fA, fw0, -1, 0);
    k_bnfin<<<1, 192>>>(0, 7, NINIT_F, fg0, fb0);

    const float* cur = fA; float* nxt = fB;
    for (int i = 0; i < 6; ++i) {
        k_conv3x3<7, false, true><<<cgrid, cblk>>>(cur, nxt, fw + (size_t)i * 441, i, i + 1);
        k_bnfin<<<1, 192>>>(i + 1, 7, NINIT_F, fg + i * 7, fb + i * 7);
        const float* tmp = cur; cur = nxt; nxt = (float*)tmp;
    }
    // after 6 swaps, cur == fA (final feature), BN stats layer 6

    // fused disp_shift + BuildCost -> cv (144 ch) in y0
    k_buildcost<<<dim3(9, 9, 2), 256, bcSmem>>>(cur, y0, bc_w, 6);

    // agg0: dw (no input act) + pw
    k_dw<<<dim3(144, 2), 256>>>(y0, y1, agg0_dw, 144, -1, 7);
    k_bnfin<<<1, 192>>>(7, 144, NAGG_F, agg0_dg, agg0_db);
    k_pw<<<dim3(144, 3, 2), 256>>>(y1, y0, agg0_pw, 144, 180, 7, 8);
    k_bnfin<<<1, 192>>>(8, 180, NAGG_F, agg0_pg, agg0_pb);

    // 4 middle blocks
    for (int i = 0; i < 4; ++i) {
        int Ld = 9 + 2 * i, Lp = 10 + 2 * i;
        k_dw<<<dim3(180, 2), 256>>>(y0, y1, aggm_dw + (size_t)i * 1620, 180, Ld - 1, Ld);
        k_bnfin<<<1, 192>>>(Ld, 180, NAGG_F, aggm_dg + i * 180, aggm_db + i * 180);
        k_pw<<<dim3(144, 3, 2), 256>>>(y1, y0, aggm_pw + (size_t)i * 32400, 180, 180, Ld, Lp);
        k_bnfin<<<1, 192>>>(Lp, 180, NAGG_F, aggm_pg + i * 180, aggm_pb + i * 180);
    }

    // last dw + final pw/softmax/expectation
    k_dw<<<dim3(180, 2), 256>>>(y0, y1, last_dw, 180, 16, 17);
    k_bnfin<<<1, 192>>>(17, 180, NAGG_F, last_dg, last_db);
    k_final<<<72, 256>>>(y1, last_pw, 17, out);
}

// round 8
// speedup vs baseline: 1.0208x; 1.0208x over previous
#include <cuda_runtime.h>
#include <math.h>

#define ANGR 9
#define NVIEW 81
#define HH 96
#define WW 96
#define HW 9216
#define CF 7
#define BB 2

static const float NINIT_F = 2.0f * 81.0f * 9216.0f;  // 1492992
static const float NAGG_F  = 2.0f * 9216.0f;          // 18432

// ---------------- device scratch (no allocations allowed) ----------------
__device__ float g_fA[BB * CF * NVIEW * HW];   // 41.8 MB
__device__ float g_fB[BB * CF * NVIEW * HW];   // 41.8 MB
__device__ float g_y0[BB * 180 * HW];          // 13.3 MB
__device__ float g_y1[BB * 180 * HW];          // 13.3 MB
__device__ float g_acc[18 * 2 * 192];          // per-layer [sum, sumsq] per channel

// ---------------- zero the stat accumulators ----------------
__global__ void k_zero() {
    int t = blockIdx.x * blockDim.x + threadIdx.x;
    if (t < 18 * 2 * 192) g_acc[t] = 0.f;
}

// ---------------- inline BN finalize from batch stats ----------------
__device__ __forceinline__ void bn_from_acc(int L, float invN,
                                            const float* __restrict__ g,
                                            const float* __restrict__ b,
                                            int c, float& sc, float& sh) {
    float s = g_acc[(L * 2 + 0) * 192 + c];
    float q = g_acc[(L * 2 + 1) * 192 + c];
    float m = s * invN;
    float var = fmaxf(q * invN - m * m, 0.f);
    sc = g[c] * rsqrtf(var + 1e-5f);
    sh = b[c] - m * sc;
}

// ---------------- conv0: 1 -> 7, per-view 3x3, input from x (SAI) ---------
// block (96,2), grid (12, 81, 2). Each thread: 4 rows x 7 cout.
__global__ __launch_bounds__(192)
void k_conv0(const float* __restrict__ in, float* __restrict__ out,
             const float* __restrict__ w) {
    __shared__ float sW[63];
    __shared__ float sPart[6][14];
    int t = threadIdx.y * 96 + threadIdx.x;
    if (t < 63) sW[t] = w[t];
    __syncthreads();

    int b = blockIdx.z, view = blockIdx.y;
    int j = threadIdx.x;
    int i0 = blockIdx.x * 8 + threadIdx.y * 4;

    const float* ibase = in + (size_t)b * 864 * 864
                       + (size_t)(view / ANGR) * 96 * 864 + (size_t)(view % ANGR) * 96;

    float colv[3][6];
#pragma unroll
    for (int rr = 0; rr < 6; ++rr) {
        int i = i0 - 1 + rr;
#pragma unroll
        for (int cc = 0; cc < 3; ++cc) {
            int jj = j - 1 + cc;
            float v = 0.f;
            if (i >= 0 && i < HH && jj >= 0 && jj < WW) v = ibase[i * 864 + jj];
            colv[cc][rr] = v;
        }
    }

    float acc[CF][4];
#pragma unroll
    for (int co = 0; co < CF; ++co)
#pragma unroll
        for (int p = 0; p < 4; ++p) acc[co][p] = 0.f;

#pragma unroll
    for (int ky = 0; ky < 3; ++ky)
#pragma unroll
        for (int kx = 0; kx < 3; ++kx) {
            float wr[CF];
#pragma unroll
            for (int co = 0; co < CF; ++co) wr[co] = sW[co * 9 + ky * 3 + kx];
#pragma unroll
            for (int p = 0; p < 4; ++p) {
                float v = colv[kx][p + ky];
#pragma unroll
                for (int co = 0; co < CF; ++co)
                    acc[co][p] = fmaf(v, wr[co], acc[co][p]);
            }
        }

    float ls[CF], ls2[CF];
#pragma unroll
    for (int co = 0; co < CF; ++co) { ls[co] = 0.f; ls2[co] = 0.f; }
#pragma unroll
    for (int co = 0; co < CF; ++co) {
        float* op = out + ((size_t)(b * CF + co) * NVIEW + view) * HW + j;
#pragma unroll
        for (int p = 0; p < 4; ++p) {
            float y = acc[co][p];
            op[(i0 + p) * WW] = y;
            ls[co] += y; ls2[co] += y * y;
        }
    }
    int lane = t & 31, warp = t >> 5;
#pragma unroll
    for (int co = 0; co < CF; ++co) {
        float s = ls[co], q = ls2[co];
#pragma unroll
        for (int off = 16; off > 0; off >>= 1) {
            s += __shfl_xor_sync(0xffffffffu, s, off);
            q += __shfl_xor_sync(0xffffffffu, q, off);
        }
        if (lane == 0) { sPart[warp][co] = s; sPart[warp][7 + co] = q; }
    }
    __syncthreads();
    if (t < 14) {
        float tot = 0.f;
#pragma unroll
        for (int wp = 0; wp < 6; ++wp) tot += sPart[wp][t];
        atomicAdd(&g_acc[(0 * 2 + (t / 7)) * 192 + (t % 7)], tot);
    }
}

// ---------------- conv7: 7 -> 7 per-view 3x3, smem input tile --------------
// block (96,2), grid (12, 81, 2). smem tile: BN+ReLU applied once at fill.
__global__ __launch_bounds__(192)
void k_conv7(const float* __restrict__ in, float* __restrict__ out,
             const float* __restrict__ w,
             const float* __restrict__ gIn, const float* __restrict__ bIn,
             int Lin, int statL) {
    __shared__ float sIn[7][10][100];   // 7000 floats
    __shared__ float sW[441];
    __shared__ float sSc[7], sSh[7];
    __shared__ float sPart[6][14];

    int t = threadIdx.y * 96 + threadIdx.x;
    if (t < 7) {
        float sc, sh;
        bn_from_acc(Lin, 1.f / NINIT_F, gIn, bIn, t, sc, sh);
        sSc[t] = sc; sSh[t] = sh;
    }
    for (int s = t; s < 441; s += 192) sW[s] = w[s];
    __syncthreads();

    int b = blockIdx.z, view = blockIdx.y;
    int i0 = blockIdx.x * 8;
    const float* ib = in + ((size_t)(b * CF) * NVIEW + view) * HW;

    // fill 7 x 10 x 100 zero-padded tile, BN+ReLU at load
    for (int s = t; s < 7000; s += 192) {
        int c = s / 1000;
        int rem = s - c * 1000;
        int r = rem / 100;
        int col = rem - r * 100;
        int ii = i0 - 1 + r, jj = col - 1;
        float v = 0.f;
        if (ii >= 0 && ii < HH && jj >= 0 && jj < WW) {
            v = ib[(size_t)c * NVIEW * HW + ii * WW + jj];
            v = fmaxf(fmaf(v, sSc[c], sSh[c]), 0.f);
        }
        ((float*)sIn)[s] = v;
    }
    __syncthreads();

    int j = threadIdx.x;
    int r0 = threadIdx.y * 4;

    float acc[CF][4];
#pragma unroll
    for (int co = 0; co < CF; ++co)
#pragma unroll
        for (int p = 0; p < 4; ++p) acc[co][p] = 0.f;

    for (int cin = 0; cin < CF; ++cin) {
        float colv[3][6];
#pragma unroll
        for (int rr = 0; rr < 6; ++rr)
#pragma unroll
            for (int cc = 0; cc < 3; ++cc)
                colv[cc][rr] = sIn[cin][r0 + rr][j + cc];
#pragma unroll
        for (int ky = 0; ky < 3; ++ky)
#pragma unroll
            for (int kx = 0; kx < 3; ++kx) {
                float wr[CF];
#pragma unroll
                for (int co = 0; co < CF; ++co)
                    wr[co] = sW[((co * CF + cin) * 3 + ky) * 3 + kx];
#pragma unroll
                for (int p = 0; p < 4; ++p) {
                    float v = colv[kx][p + ky];
#pragma unroll
                    for (int co = 0; co < CF; ++co)
                        acc[co][p] = fmaf(v, wr[co], acc[co][p]);
                }
            }
    }

    int iout = i0 + r0;
    float ls[CF], ls2[CF];
#pragma unroll
    for (int co = 0; co < CF; ++co) { ls[co] = 0.f; ls2[co] = 0.f; }
#pragma unroll
    for (int co = 0; co < CF; ++co) {
        float* op = out + ((size_t)(b * CF + co) * NVIEW + view) * HW + j;
#pragma unroll
        for (int p = 0; p < 4; ++p) {
            float y = acc[co][p];
            op[(iout + p) * WW] = y;
            ls[co] += y; ls2[co] += y * y;
        }
    }

    int lane = t & 31, warp = t >> 5;
#pragma unroll
    for (int co = 0; co < CF; ++co) {
        float s = ls[co], q = ls2[co];
#pragma unroll
        for (int off = 16; off > 0; off >>= 1) {
            s += __shfl_xor_sync(0xffffffffu, s, off);
            q += __shfl_xor_sync(0xffffffffu, q, off);
        }
        if (lane == 0) { sPart[warp][co] = s; sPart[warp][7 + co] = q; }
    }
    __syncthreads();
    if (t < 14) {
        float tot = 0.f;
#pragma unroll
        for (int wp = 0; wp < 6; ++wp) tot += sPart[wp][t];
        atomicAdd(&g_acc[(statL * 2 + (t / 7)) * 192 + (t % 7)], tot);
    }
}

// ---------------- fused disp_shift + BuildCost (plane sweep) ----------------
__global__ __launch_bounds__(256)
void k_buildcost(const float* __restrict__ f, float* __restrict__ cv,
                 const float* __restrict__ bcw,
                 const float* __restrict__ g6, const float* __restrict__ b6) {
    extern __shared__ float sm[];
    float* sW = sm;            // 81*7*16 = 9072 floats
    float* sT = sm + 9072;     // 7*32*32 = 7168 floats
    __shared__ float sSc[CF], sSh[CF];

    int t = threadIdx.x;
    int b = blockIdx.z, g = blockIdx.y;
    int d = g - 4;
    int y0 = (blockIdx.x / 3) * 32, x0 = (blockIdx.x % 3) * 32;

    if (t < CF) {
        float sc, sh;
        bn_from_acc(6, 1.f / NINIT_F, g6, b6, t, sc, sh);
        sSc[t] = sc; sSh[t] = sh;
    }
    for (int s = t; s < 9072; s += 256) {
        int o = s & 15;
        int c = (s >> 4) % 7;
        int uv = s / 112;
        int u = uv / 9, v = uv % 9;
        int uvs = (d > 0) ? ((8 - u) * 9 + (8 - v)) : uv;
        sW[s] = bcw[((size_t)(16 * g + o) * 7 + c) * 81 + uvs];
    }
    __syncthreads();

    int tx = t & 31, ty0 = t >> 5;
    float acc[4][16];
#pragma unroll
    for (int p = 0; p < 4; ++p)
#pragma unroll
        for (int o = 0; o < 16; ++o) acc[p][o] = 0.f;

    const float* fb = f + (size_t)b * CF * NVIEW * HW;

    for (int uv = 0; uv < 81; ++uv) {
        int u = uv / 9, v = uv % 9;
        int sy = y0 - d * (u - 4), sx = x0 - d * (v - 4);
        for (int s = t; s < 7168; s += 256) {
            int c = s >> 10;
            int pp = s & 1023;
            int r = pp >> 5, cc = pp & 31;
            int ii = sy + r, jj = sx + cc;
            float val = 0.f;
            if (ii >= 0 && ii < HH && jj >= 0 && jj < WW)
                val = fmaxf(fmaf(fb[((size_t)c * NVIEW + uv) * HW + ii * WW + jj],
                                 sSc[c], sSh[c]), 0.f);
            sT[s] = val;
        }
        __syncthreads();
        const float* wuv = sW + uv * 112;
#pragma unroll
        for (int c = 0; c < 7; ++c) {
            float wr[16];
#pragma unroll
            for (int o = 0; o < 16; ++o) wr[o] = wuv[c * 16 + o];
#pragma unroll
            for (int p = 0; p < 4; ++p) {
                float v = sT[c * 1024 + (ty0 + 8 * p) * 32 + tx];
#pragma unroll
                for (int o = 0; o < 16; ++o)
                    acc[p][o] = fmaf(v, wr[o], acc[p][o]);
            }
        }
        __syncthreads();
    }

#pragma unroll
    for (int o = 0; o < 16; ++o) {
        float* op = cv + ((size_t)b * 144 + 16 * g + o) * HW;
#pragma unroll
        for (int p = 0; p < 4; ++p)
            op[(y0 + ty0 + 8 * p) * WW + (x0 + tx)] = acc[p][o];
    }
}

// ---------------- depthwise 3x3 (pad 1), optional input BN+ReLU ------------
__global__ __launch_bounds__(256)
void k_dw(const float* __restrict__ in, float* __restrict__ out,
          const float* __restrict__ w, int C, int Lin, float invN,
          const float* __restrict__ gIn, const float* __restrict__ bIn,
          int statL) {
    int c = blockIdx.x, b = blockIdx.y, t = threadIdx.x;
    float wr[9];
#pragma unroll
    for (int k = 0; k < 9; ++k) wr[k] = w[c * 9 + k];
    float sc = 1.f, sh = 0.f;
    bool act = (Lin >= 0);
    if (act) bn_from_acc(Lin, invN, gIn, bIn, c, sc, sh);
    const float* ip = in + ((size_t)b * C + c) * HW;
    float* op = out + ((size_t)b * C + c) * HW;
    float ls = 0.f, ls2 = 0.f;
    for (int p = t; p < HW; p += 256) {
        int i = p / 96, j = p - i * 96;
        float sum = 0.f;
#pragma unroll
        for (int dy = -1; dy <= 1; ++dy)
#pragma unroll
            for (int dx = -1; dx <= 1; ++dx) {
                int ii = i + dy, jj = j + dx;
                if (ii >= 0 && ii < HH && jj >= 0 && jj < WW) {
                    float v = ip[ii * WW + jj];
                    if (act) v = fmaxf(fmaf(v, sc, sh), 0.f);
                    sum = fmaf(v, wr[(dy + 1) * 3 + dx + 1], sum);
                }
            }
        op[p] = sum; ls += sum; ls2 += sum * sum;
    }
    __shared__ float sP[8][2];
    int lane = t & 31, wp = t >> 5;
#pragma unroll
    for (int off = 16; off > 0; off >>= 1) {
        ls  += __shfl_xor_sync(0xffffffffu, ls, off);
        ls2 += __shfl_xor_sync(0xffffffffu, ls2, off);
    }
    if (lane == 0) { sP[wp][0] = ls; sP[wp][1] = ls2; }
    __syncthreads();
    if (t == 0) {
        float a = 0.f, q = 0.f;
#pragma unroll
        for (int k = 0; k < 8; ++k) { a += sP[k][0]; q += sP[k][1]; }
        atomicAdd(&g_acc[(statL * 2 + 0) * 192 + c], a);
        atomicAdd(&g_acc[(statL * 2 + 1) * 192 + c], q);
    }
}

// ---------------- pointwise conv = GEMM [Cout x Cin] x [Cin x 9216] --------
__global__ __launch_bounds__(256)
void k_pw(const float* __restrict__ in, float* __restrict__ out,
          const float* __restrict__ w, int Cin, int Cout, int Lin,
          const float* __restrict__ gIn, const float* __restrict__ bIn,
          int statL) {
    __shared__ __align__(16) float sA[16 * 64];
    __shared__ __align__(16) float sB[16 * 64];
    __shared__ float sSc[192], sSh[192];
    int t = threadIdx.x;
    int n0 = blockIdx.x * 64, m0 = blockIdx.y * 64, b = blockIdx.z;
    for (int c = t; c < Cin; c += 256) {
        float sc, sh;
        bn_from_acc(Lin, 1.f / NAGG_F, gIn, bIn, c, sc, sh);
        sSc[c] = sc; sSh[c] = sh;
    }
    int tm = (t >> 4) << 2, tn = (t & 15) << 2;
    float acc[4][4];
#pragma unroll
    for (int i2 = 0; i2 < 4; ++i2)
#pragma unroll
        for (int j2 = 0; j2 < 4; ++j2) acc[i2][j2] = 0.f;
    int Kt = (Cin + 15) >> 4;
    __syncthreads();
    for (int kt = 0; kt < Kt; ++kt) {
        int k0 = kt << 4;
#pragma unroll
        for (int r = 0; r < 4; ++r) {
            int s = t + r * 256;
            int k = s >> 6, mn = s & 63;
            int ci = k0 + k;
            int co = m0 + mn;
            sA[s] = (ci < Cin && co < Cout) ? w[(size_t)co * Cin + ci] : 0.f;
            float xv = 0.f;
            if (ci < Cin)
                xv = fmaxf(fmaf(in[((size_t)b * Cin + ci) * HW + n0 + mn], sSc[ci], sSh[ci]), 0.f);
            sB[s] = xv;
        }
        __syncthreads();
#pragma unroll
        for (int kk = 0; kk < 16; ++kk) {
            float4 av = *reinterpret_cast<const float4*>(&sA[kk * 64 + tm]);
            float4 bv = *reinterpret_cast<const float4*>(&sB[kk * 64 + tn]);
            float a[4] = {av.x, av.y, av.z, av.w};
            float bb2[4] = {bv.x, bv.y, bv.z, bv.w};
#pragma unroll
            for (int i2 = 0; i2 < 4; ++i2)
#pragma unroll
                for (int j2 = 0; j2 < 4; ++j2)
                    acc[i2][j2] = fmaf(a[i2], bb2[j2], acc[i2][j2]);
        }
        __syncthreads();
    }
    float ls[4], ls2[4];
#pragma unroll
    for (int i2 = 0; i2 < 4; ++i2) { ls[i2] = 0.f; ls2[i2] = 0.f; }
#pragma unroll
    for (int i2 = 0; i2 < 4; ++i2) {
        int co = m0 + tm + i2;
        if (co < Cout) {
            float* op = out + ((size_t)b * Cout + co) * HW + n0 + tn;
#pragma unroll
            for (int j2 = 0; j2 < 4; ++j2) {
                float y = acc[i2][j2];
                op[j2] = y; ls[i2] += y; ls2[i2] += y * y;
            }
        }
    }
    if (statL >= 0) {
#pragma unroll
        for (int i2 = 0; i2 < 4; ++i2) {
            float s = ls[i2], q = ls2[i2];
#pragma unroll
            for (int off = 8; off > 0; off >>= 1) {
                s += __shfl_xor_sync(0xffffffffu, s, off);
                q += __shfl_xor_sync(0xffffffffu, q, off);
            }
            if ((t & 15) == 0) {
                int co = m0 + tm + i2;
                if (co < Cout) {
                    atomicAdd(&g_acc[(statL * 2 + 0) * 192 + co], s);
                    atomicAdd(&g_acc[(statL * 2 + 1) * 192 + co], q);
                }
            }
        }
    }
}

// ---------------- final: pw 180->9 + softmax + disparity expectation -------
__global__ __launch_bounds__(256)
void k_final(const float* __restrict__ in, const float* __restrict__ w,
             const float* __restrict__ gIn, const float* __restrict__ bIn,
             float* __restrict__ out) {
    __shared__ float sW[9 * 180];
    __shared__ float sSc[180], sSh[180];
    int t = threadIdx.x;
    for (int s = t; s < 9 * 180; s += 256) sW[s] = w[s];
    for (int c = t; c < 180; c += 256) {
        float sc, sh;
        bn_from_acc(17, 1.f / NAGG_F, gIn, bIn, c, sc, sh);
        sSc[c] = sc; sSh[c] = sh;
    }
    __syncthreads();
    int pix = blockIdx.x * 256 + t;
    int b = pix / HW, p = pix - b * HW;
    float a[9];
#pragma unroll
    for (int c = 0; c < 9; ++c) a[c] = 0.f;
    for (int ci = 0; ci < 180; ++ci) {
        float v = fmaxf(fmaf(in[((size_t)b * 180 + ci) * HW + p], sSc[ci], sSh[ci]), 0.f);
#pragma unroll
        for (int c = 0; c < 9; ++c) a[c] = fmaf(v, sW[c * 180 + ci], a[c]);
    }
    float m = a[0];
#pragma unroll
    for (int c = 1; c < 9; ++c) m = fmaxf(m, a[c]);
    float den = 0.f, num = 0.f;
#pragma unroll
    for (int c = 0; c < 9; ++c) {
        float e = expf(a[c] - m);
        den += e; num += e * (float)(c - 4);
    }
    out[pix] = num / den;
}

// ------------------------------------------------------------------------
extern "C" void kernel_launch(void* const* d_in, const int* in_sizes, int n_in,
                              void* d_out, int out_size) {
    (void)in_sizes; (void)n_in; (void)out_size;
    const float* x       = (const float*)d_in[0];
    const float* fw0     = (const float*)d_in[1];
    const float* fg0     = (const float*)d_in[2];
    const float* fb0     = (const float*)d_in[3];
    const float* fw      = (const float*)d_in[4];
    const float* fg      = (const float*)d_in[5];
    const float* fb      = (const float*)d_in[6];
    const float* bc_w    = (const float*)d_in[7];
    const float* agg0_dw = (const float*)d_in[8];
    const float* agg0_dg = (const float*)d_in[9];
    const float* agg0_db = (const float*)d_in[10];
    const float* agg0_pw = (const float*)d_in[11];
    const float* agg0_pg = (const float*)d_in[12];
    const float* agg0_pb = (const float*)d_in[13];
    const float* aggm_dw = (const float*)d_in[14];
    const float* aggm_dg = (const float*)d_in[15];
    const float* aggm_db = (const float*)d_in[16];
    const float* aggm_pw = (const float*)d_in[17];
    const float* aggm_pg = (const float*)d_in[18];
    const float* aggm_pb = (const float*)d_in[19];
    const float* last_dw = (const float*)d_in[20];
    const float* last_dg = (const float*)d_in[21];
    const float* last_db = (const float*)d_in[22];
    const float* last_pw = (const float*)d_in[23];
    float* out = (float*)d_out;

    float *fA, *fB, *y0, *y1;
    cudaGetSymbolAddress((void**)&fA, g_fA);
    cudaGetSymbolAddress((void**)&fB, g_fB);
    cudaGetSymbolAddress((void**)&y0, g_y0);
    cudaGetSymbolAddress((void**)&y1, g_y1);

    const int bcSmem = (9072 + 7168) * 4;  // 64960 bytes
    cudaFuncSetAttribute(k_buildcost, cudaFuncAttributeMaxDynamicSharedMemorySize, bcSmem);

    k_zero<<<27, 256>>>();

    dim3 cgrid(12, 81, 2), cblk(96, 2);
    // conv0: 1 -> 7, input from x (SAI layout), stats layer 0
    k_conv0<<<cgrid, cblk>>>(x, fA, fw0);

    const float* cur = fA; float* nxt = fB;
    for (int i = 0; i < 6; ++i) {
        const float* gi = (i == 0) ? fg0 : (fg + (size_t)(i - 1) * 7);
        const float* bi = (i == 0) ? fb0 : (fb + (size_t)(i - 1) * 7);
        k_conv7<<<cgrid, cblk>>>(cur, nxt, fw + (size_t)i * 441, gi, bi, i, i + 1);
        const float* tmp = cur; cur = nxt; nxt = (float*)tmp;
    }
    // cur holds final pre-activation features; stats in layer 6 (gamma = fg[5])

    // fused disp_shift + BuildCost -> cv (144 ch) in y0
    k_buildcost<<<dim3(9, 9, 2), 256, bcSmem>>>(cur, y0, bc_w, fg + 35, fb + 35);

    // agg0: dw (no input act) + pw
    k_dw<<<dim3(144, 2), 256>>>(y0, y1, agg0_dw, 144, -1, 0.f, nullptr, nullptr, 7);
    k_pw<<<dim3(144, 3, 2), 256>>>(y1, y0, agg0_pw, 144, 180, 7, agg0_dg, agg0_db, 8);

    // 4 middle blocks
    for (int i = 0; i < 4; ++i) {
        int Ld = 9 + 2 * i, Lp = 10 + 2 * i;
        const float* gp = (i == 0) ? agg0_pg : (aggm_pg + (size_t)(i - 1) * 180);
        const float* bp = (i == 0) ? agg0_pb : (aggm_pb + (size_t)(i - 1) * 180);
        k_dw<<<dim3(180, 2), 256>>>(y0, y1, aggm_dw + (size_t)i * 1620, 180,
                                    Ld - 1, 1.f / NAGG_F, gp, bp, Ld);
        k_pw<<<dim3(144, 3, 2), 256>>>(y1, y0, aggm_pw + (size_t)i * 32400, 180, 180,
                                       Ld, aggm_dg + (size_t)i * 180, aggm_db + (size_t)i * 180, Lp);
    }

    // last dw + final pw/softmax/expectation
    k_dw<<<dim3(180, 2), 256>>>(y0, y1, last_dw, 180, 16, 1.f / NAGG_F,
                                aggm_pg + 3 * 180, aggm_pb + 3 * 180, 17);
    k_final<<<72, 256>>>(y1, last_pw, last_dg, last_db, out);
}